// round 7
// baseline (speedup 1.0000x reference)
#include <cuda_runtime.h>
#include <math.h>

// Problem constants
#define NROWS 512      // B*N = 16*32
#define NO 128         // node out dim
#define EH 256         // edge/node hidden dim
#define TSTEPS 25

// Scratch (device globals: no allocation allowed)
__device__ float g_x[NROWS * NO];     // node features / GRU hidden
__device__ float g_P[NROWS * EH];     // x @ W1_top   (send half)
__device__ float g_Q[NROWS * EH];     // x @ W1_bot   (rec half)
__device__ float g_msg[NROWS * NO];   // edge2node mean message

// ---------------------------------------------------------------------------
// Edge kernel: for block (b, n) [n = receiver], compute for all 32 senders s:
//   h1[s][k] = ReLU(P[b,s,k] + Q[b,n,k] + b1[k])
//   out[s][c] = ReLU(h1[s] @ W2[:,c] + b2[c])
//   msg[b,n,c] = mean_{s != n} out[s][c]
// 256 threads: c = tid&127 owns output column, g = tid>>7 owns sender half.
// All shared-memory reads in the GEMM are warp-uniform (broadcast, conflict-free).
// ---------------------------------------------------------------------------
__global__ __launch_bounds__(256) void edge_kernel(
    const float* __restrict__ b1,   // [256]
    const float* __restrict__ W2,   // [256,128] row-major
    const float* __restrict__ b2)   // [128]
{
    __shared__ float A[32][EH];       // 32 KB: ReLU'd layer-1 activations
    __shared__ float qb[EH];          // Q[b,n,:] + b1
    __shared__ float sum2[2][128];

    const int bn  = blockIdx.x;
    const int b   = bn >> 5;
    const int n   = bn & 31;
    const int tid = threadIdx.x;

    const float* Qn = g_Q + bn * EH;
    if (tid < EH) qb[tid] = Qn[tid] + b1[tid];
    __syncthreads();

    // Fill A (vectorized, 8 float4 per thread)
    const float* Pb = g_P + b * 32 * EH;
    for (int idx = tid; idx < 32 * (EH / 4); idx += 256) {
        int s = idx >> 6, q = idx & 63;
        float4 p  = ((const float4*)(Pb + s * EH))[q];
        float4 qv = ((const float4*)qb)[q];
        float4 a;
        a.x = fmaxf(p.x + qv.x, 0.f);
        a.y = fmaxf(p.y + qv.y, 0.f);
        a.z = fmaxf(p.z + qv.z, 0.f);
        a.w = fmaxf(p.w + qv.w, 0.f);
        ((float4*)&A[s][0])[q] = a;
    }
    __syncthreads();

    const int c = tid & 127;
    const int g = tid >> 7;

    float acc[16];
#pragma unroll
    for (int i = 0; i < 16; i++) acc[i] = 0.f;

    const float* w2c = W2 + c;
#pragma unroll 2
    for (int k4 = 0; k4 < EH / 4; k4++) {
        const int k = k4 * 4;
        float w0 = w2c[(k + 0) * 128];
        float w1v = w2c[(k + 1) * 128];
        float w2v = w2c[(k + 2) * 128];
        float w3 = w2c[(k + 3) * 128];
#pragma unroll
        for (int i = 0; i < 16; i++) {
            float4 a = ((const float4*)&A[g * 16 + i][0])[k4];
            acc[i] = fmaf(a.x, w0, acc[i]);
            acc[i] = fmaf(a.y, w1v, acc[i]);
            acc[i] = fmaf(a.z, w2v, acc[i]);
            acc[i] = fmaf(a.w, w3, acc[i]);
        }
    }

    float bias = b2[c];
    float partial = 0.f;
#pragma unroll
    for (int i = 0; i < 16; i++) {
        int s = g * 16 + i;
        float o = fmaxf(acc[i] + bias, 0.f);
        if (s != n) partial += o;   // exclude self-edge (s == rec)
    }
    sum2[g][c] = partial;
    __syncthreads();

    if (tid < 128)
        g_msg[bn * 128 + tid] = (sum2[0][tid] + sum2[1][tid]) * (1.0f / 31.0f);
}

// ---------------------------------------------------------------------------
// Fused MLP kernel (encoder mlp1 / passing node MLP) + next-stage P/Q:
//   x = ReLU(ReLU(in @ w1 + b1) @ w2 + b2)         (K1 -> 256 -> 128)
//   P = x @ w1n[0:128,:],  Q = x @ w1n[128:256,:]
// 8 rows per block (amortizes weight traffic), 64 blocks, 256 threads.
// ---------------------------------------------------------------------------
template<int K1, bool FROM_MSG>
__global__ __launch_bounds__(256) void mlp_pq_kernel(
    const float* __restrict__ in_ext,
    const float* __restrict__ w1, const float* __restrict__ b1,   // [K1,256],[256]
    const float* __restrict__ w2, const float* __restrict__ b2,   // [256,128],[128]
    const float* __restrict__ w1n)                                // [256,256]
{
    __shared__ float in_s[8][K1];
    __shared__ float hid[8][EH];
    __shared__ float xs[8][NO];

    const int tid  = threadIdx.x;
    const int row0 = blockIdx.x * 8;
    const float* in = FROM_MSG ? g_msg : in_ext;

    for (int idx = tid; idx < 8 * K1; idx += 256) {
        int r = idx / K1, k = idx - r * K1;
        in_s[r][k] = in[(row0 + r) * K1 + k];
    }
    __syncthreads();

    // layer 1: K1 -> 256
    {
        const int j = tid;
        float acc[8];
#pragma unroll
        for (int r = 0; r < 8; r++) acc[r] = 0.f;
#pragma unroll 2
        for (int k = 0; k < K1; k++) {
            float w = w1[k * EH + j];
#pragma unroll
            for (int r = 0; r < 8; r++) acc[r] = fmaf(in_s[r][k], w, acc[r]);
        }
        float bb = b1[j];
#pragma unroll
        for (int r = 0; r < 8; r++) hid[r][j] = fmaxf(acc[r] + bb, 0.f);
    }
    __syncthreads();

    // layer 2: 256 -> 128
    {
        const int c = tid & 127, g = tid >> 7;
        float acc[4] = {0.f, 0.f, 0.f, 0.f};
#pragma unroll 2
        for (int k = 0; k < EH; k++) {
            float w = w2[k * NO + c];
#pragma unroll
            for (int r = 0; r < 4; r++) acc[r] = fmaf(hid[g * 4 + r][k], w, acc[r]);
        }
        float bb = b2[c];
#pragma unroll
        for (int r = 0; r < 4; r++) {
            float o = fmaxf(acc[r] + bb, 0.f);
            xs[g * 4 + r][c] = o;
            g_x[(row0 + g * 4 + r) * NO + c] = o;
        }
    }
    __syncthreads();

    // next-stage P/Q
    {
        const int j = tid;
        float accP[8], accQ[8];
#pragma unroll
        for (int r = 0; r < 8; r++) { accP[r] = 0.f; accQ[r] = 0.f; }
#pragma unroll 2
        for (int k = 0; k < NO; k++) {
            float wp = w1n[k * EH + j];
            float wq = w1n[(128 + k) * EH + j];
#pragma unroll
            for (int r = 0; r < 8; r++) {
                float xv = xs[r][k];
                accP[r] = fmaf(xv, wp, accP[r]);
                accQ[r] = fmaf(xv, wq, accQ[r]);
            }
        }
#pragma unroll
        for (int r = 0; r < 8; r++) {
            g_P[(row0 + r) * EH + j] = accP[r];
            g_Q[(row0 + r) * EH + j] = accQ[r];
        }
    }
}

// ---------------------------------------------------------------------------
// GRU step kernel: 8 rows/block, 64 blocks, 256 threads.
//   ni = [msg(128), inp(3)]
//   r = sig(ni@w_ir + b_ir + h@w_hr); i = sig(ni@w_ii + b_ii + h@w_hi)
//   n = tanh(ni@w_in + b_in + r*(h@w_hn)); h' = (1-i)*n + i*h
// Then fused next-step P/Q from h'.
// ---------------------------------------------------------------------------
__global__ __launch_bounds__(256) void gru_kernel(
    const float* __restrict__ dec_t,   // [512,3] slice for this t
    const float* __restrict__ w_hr, const float* __restrict__ w_hi, const float* __restrict__ w_hn,
    const float* __restrict__ w_ir, const float* __restrict__ b_ir,
    const float* __restrict__ w_ii, const float* __restrict__ b_ii,
    const float* __restrict__ w_in, const float* __restrict__ b_in,
    const float* __restrict__ w1n,    // de_w1 for next step
    float* __restrict__ out_t,        // outputs[t] = [512,128]
    float* __restrict__ state)        // final state (or nullptr)
{
    __shared__ float m_s[8][NO];
    __shared__ float h_s[8][NO];
    __shared__ float inp_s[8][3];
    __shared__ float hn_s[8][NO];

    const int tid  = threadIdx.x;
    const int row0 = blockIdx.x * 8;

    for (int idx = tid; idx < 8 * NO; idx += 256) {
        int r = idx >> 7, k = idx & 127;
        m_s[r][k] = g_msg[(row0 + r) * NO + k];
        h_s[r][k] = g_x[(row0 + r) * NO + k];
    }
    if (tid < 24) {
        int r = tid / 3, j = tid - r * 3;
        inp_s[r][j] = dec_t[(row0 + r) * 3 + j];
    }
    __syncthreads();

    const int c = tid & 127, g = tid >> 7;
    float a_ir[4] = {0,0,0,0}, a_ii[4] = {0,0,0,0}, a_in[4] = {0,0,0,0};
    float a_hr[4] = {0,0,0,0}, a_hi[4] = {0,0,0,0}, a_hn[4] = {0,0,0,0};

#pragma unroll 2
    for (int k = 0; k < NO; k++) {
        float wir = w_ir[k * 128 + c], wii = w_ii[k * 128 + c], win = w_in[k * 128 + c];
        float whr = w_hr[k * 128 + c], whi = w_hi[k * 128 + c], whn = w_hn[k * 128 + c];
#pragma unroll
        for (int r = 0; r < 4; r++) {
            float m  = m_s[g * 4 + r][k];
            float hh = h_s[g * 4 + r][k];
            a_ir[r] = fmaf(m, wir, a_ir[r]);
            a_ii[r] = fmaf(m, wii, a_ii[r]);
            a_in[r] = fmaf(m, win, a_in[r]);
            a_hr[r] = fmaf(hh, whr, a_hr[r]);
            a_hi[r] = fmaf(hh, whi, a_hi[r]);
            a_hn[r] = fmaf(hh, whn, a_hn[r]);
        }
    }
#pragma unroll
    for (int j = 0; j < 3; j++) {
        float wir = w_ir[(128 + j) * 128 + c];
        float wii = w_ii[(128 + j) * 128 + c];
        float win = w_in[(128 + j) * 128 + c];
#pragma unroll
        for (int r = 0; r < 4; r++) {
            float x = inp_s[g * 4 + r][j];
            a_ir[r] = fmaf(x, wir, a_ir[r]);
            a_ii[r] = fmaf(x, wii, a_ii[r]);
            a_in[r] = fmaf(x, win, a_in[r]);
        }
    }

    float bir = b_ir[c], bii = b_ii[c], bin = b_in[c];
#pragma unroll
    for (int r = 0; r < 4; r++) {
        int row = g * 4 + r;
        float rr = 1.f / (1.f + expf(-(a_ir[r] + bir + a_hr[r])));
        float ii = 1.f / (1.f + expf(-(a_ii[r] + bii + a_hi[r])));
        float nn = tanhf(a_in[r] + bin + rr * a_hn[r]);
        float hv = (1.f - ii) * nn + ii * h_s[row][c];
        hn_s[row][c] = hv;
        int grow = row0 + row;
        g_x[grow * NO + c] = hv;
        out_t[grow * NO + c] = hv;
        if (state) state[grow * NO + c] = hv;
    }
    __syncthreads();

    // fused next-step P/Q from h'
    {
        const int j = tid;
        float accP[8], accQ[8];
#pragma unroll
        for (int r = 0; r < 8; r++) { accP[r] = 0.f; accQ[r] = 0.f; }
#pragma unroll 2
        for (int k = 0; k < NO; k++) {
            float wp = w1n[k * EH + j];
            float wq = w1n[(128 + k) * EH + j];
#pragma unroll
            for (int r = 0; r < 8; r++) {
                float xv = hn_s[r][k];
                accP[r] = fmaf(xv, wp, accP[r]);
                accQ[r] = fmaf(xv, wq, accQ[r]);
            }
        }
#pragma unroll
        for (int r = 0; r < 8; r++) {
            g_P[(row0 + r) * EH + j] = accP[r];
            g_Q[(row0 + r) * EH + j] = accQ[r];
        }
    }
}

// ---------------------------------------------------------------------------
extern "C" void kernel_launch(void* const* d_in, const int* in_sizes, int n_in,
                              void* d_out, int out_size)
{
    const float* enc_in = (const float*)d_in[0];   // [16,32,150]
    const float* dec_in = (const float*)d_in[1];   // [25,16,32,3]
    // d_in[2]=rec_encode, d_in[3]=send_encode (structure hardcoded)
    const float* enc_w1 = (const float*)d_in[4];
    const float* enc_b1 = (const float*)d_in[5];
    const float* enc_w2 = (const float*)d_in[6];
    const float* enc_b2 = (const float*)d_in[7];
    const float* pe_w1  = (const float*)d_in[8];
    const float* pe_b1  = (const float*)d_in[9];
    const float* pe_w2  = (const float*)d_in[10];
    const float* pe_b2  = (const float*)d_in[11];
    const float* pn_w1  = (const float*)d_in[12];
    const float* pn_b1  = (const float*)d_in[13];
    const float* pn_w2  = (const float*)d_in[14];
    const float* pn_b2  = (const float*)d_in[15];
    const float* de_w1  = (const float*)d_in[16];
    const float* de_b1  = (const float*)d_in[17];
    const float* de_w2  = (const float*)d_in[18];
    const float* de_b2  = (const float*)d_in[19];
    const float* w_hr   = (const float*)d_in[20];
    const float* w_hi   = (const float*)d_in[21];
    const float* w_hn   = (const float*)d_in[22];
    const float* w_ir   = (const float*)d_in[23];
    const float* b_ir   = (const float*)d_in[24];
    const float* w_ii   = (const float*)d_in[25];
    const float* b_ii   = (const float*)d_in[26];
    const float* w_in   = (const float*)d_in[27];
    const float* b_in   = (const float*)d_in[28];

    float* out   = (float*)d_out;
    float* state = out + (size_t)TSTEPS * NROWS * NO;  // outputs then final state

    // Encoder: mlp1, then P/Q for pass round 1 (pe_w1)
    mlp_pq_kernel<150, false><<<64, 256>>>(enc_in, enc_w1, enc_b1, enc_w2, enc_b2, pe_w1);

    // Two message-passing rounds
    for (int p = 0; p < 2; p++) {
        edge_kernel<<<512, 256>>>(pe_b1, pe_w2, pe_b2);
        mlp_pq_kernel<128, true><<<64, 256>>>(nullptr, pn_w1, pn_b1, pn_w2, pn_b2,
                                              (p == 0) ? pe_w1 : de_w1);
    }

    // Decoder: 25 GRU steps (each: edge message pass -> gated update -> next P/Q)
    for (int t = 0; t < TSTEPS; t++) {
        edge_kernel<<<512, 256>>>(de_b1, de_w2, de_b2);
        gru_kernel<<<64, 256>>>(dec_in + (size_t)t * NROWS * 3,
                                w_hr, w_hi, w_hn, w_ir, b_ir, w_ii, b_ii, w_in, b_in,
                                de_w1,
                                out + (size_t)t * NROWS * NO,
                                (t == TSTEPS - 1) ? state : nullptr);
    }
}

// round 8
// speedup vs baseline: 1.2305x; 1.2305x over previous
#include <cuda_runtime.h>
#include <cuda_bf16.h>
#include <math.h>
#include <stdint.h>

// Problem constants
#define NROWS 512      // B*N = 16*32
#define NO 128         // node out dim
#define EH 256         // edge/node hidden dim
#define TSTEPS 25

// Scratch (device globals: no allocation allowed)
__device__ float g_x[NROWS * NO];        // node features / GRU hidden
__device__ float g_P[NROWS * EH];        // x @ W1_top   (send half)
__device__ float g_Q[NROWS * EH];        // x @ W1_bot   (rec half)
__device__ float g_msg[NROWS * NO];      // edge2node mean message
// Packed bf16 hi/lo of edge layer-2 weights (mat 0 = pe_w2, 1 = de_w2).
// Layout: [kpair r (= k/2)][n]: u32 = bf16x2 {W[2r][n], W[2r+1][n]}
__device__ uint32_t g_Whi[2][128 * 128];
__device__ uint32_t g_Wlo[2][128 * 128];

// ---------------------------------------------------------------------------
// Pack pe_w2 / de_w2 into bf16 hi/lo k-pair format (runs first, every launch).
// ---------------------------------------------------------------------------
__global__ void pack_w2_kernel(const float* __restrict__ w2a,
                               const float* __restrict__ w2b)
{
    int idx = blockIdx.x * blockDim.x + threadIdx.x;   // < 32768
    int mat = idx >> 14;
    int rem = idx & 16383;
    int r = rem >> 7, n = rem & 127;
    const float* W = mat ? w2b : w2a;
    float w0 = W[(2 * r) * 128 + n];
    float w1 = W[(2 * r + 1) * 128 + n];
    __nv_bfloat162 h2 = __floats2bfloat162_rn(w0, w1);
    float l0 = w0 - __low2float(h2);
    float l1 = w1 - __high2float(h2);
    __nv_bfloat162 l2 = __floats2bfloat162_rn(l0, l1);
    g_Whi[mat][r * 128 + n] = *reinterpret_cast<uint32_t*>(&h2);
    g_Wlo[mat][r * 128 + n] = *reinterpret_cast<uint32_t*>(&l2);
}

__device__ __forceinline__ void mma_bf16(float (&d)[4], const uint32_t (&a)[4],
                                         uint32_t b0, uint32_t b1)
{
    asm volatile(
        "mma.sync.aligned.m16n8k16.row.col.f32.bf16.bf16.f32 "
        "{%0,%1,%2,%3}, {%4,%5,%6,%7}, {%8,%9}, {%0,%1,%2,%3};"
        : "+f"(d[0]), "+f"(d[1]), "+f"(d[2]), "+f"(d[3])
        : "r"(a[0]), "r"(a[1]), "r"(a[2]), "r"(a[3]), "r"(b0), "r"(b1));
}

// ---------------------------------------------------------------------------
// Tensor-core edge kernel. One CTA handles (b, n0) and (b, n0+1): M = 64 rows
// (2 receivers x 32 senders), N = 128 cols, K = 256, bf16 hi/lo split (3 MMAs).
//   A[row][k] = ReLU(P[b,send,k] + Q[b,recv,k] + b1[k])   (fp32 -> bf16 hi+lo)
//   out = ReLU(A @ W2 + b2); msg[recv] = mean over senders != recv
// 8 warps: warp w -> mtile (w>>1) of 16 rows, col half (w&1) of 64 cols.
// smem: sA hi/lo [64][132] packed bf16x2, sB chunk [2][32][136], qb, red.
// ---------------------------------------------------------------------------
#define EDGE_SMEM_BYTES ((2*64*132 + 2*32*136 + 512 + 512) * 4)

__global__ __launch_bounds__(256, 2) void edge_mma_kernel(
    int mat, const float* __restrict__ b1, const float* __restrict__ b2)
{
    extern __shared__ uint32_t sm[];
    uint32_t* sA  = sm;                          // hi [64][132] then lo [64][132]
    uint32_t* sB  = sm + 2 * 64 * 132;           // [2][32][136]
    float*    qb  = (float*)(sB + 2 * 32 * 136); // [2][256]
    float*    red = qb + 512;                    // [4][128]

    const int tid = threadIdx.x;
    const int blk = blockIdx.x;
    const int b   = blk >> 4;
    const int n0  = (blk & 15) * 2;
    const int bn0 = b * 32 + n0;

    // qb[r][k] = Q[bn0+r][k] + b1[k]
#pragma unroll
    for (int i = 0; i < 2; i++) {
        int idx = tid + i * 256;
        int r = idx >> 8, k = idx & 255;
        qb[idx] = g_Q[(bn0 + r) * EH + k] + b1[k];
    }
    __syncthreads();

    // Build A (bf16 hi/lo, packed k-pairs): 64 rows x 128 pairs
#pragma unroll 4
    for (int i = 0; i < 32; i++) {
        int lin = tid + i * 256;
        int row = lin >> 7, kp = lin & 127;
        int recv = row >> 5, send = row & 31;
        float2 p = *(const float2*)(g_P + (b * 32 + send) * EH + 2 * kp);
        float2 q = *(const float2*)(qb + recv * 256 + 2 * kp);
        float a0 = fmaxf(p.x + q.x, 0.f);
        float a1 = fmaxf(p.y + q.y, 0.f);
        __nv_bfloat162 h2 = __floats2bfloat162_rn(a0, a1);
        float l0 = a0 - __low2float(h2);
        float l1 = a1 - __high2float(h2);
        __nv_bfloat162 l2 = __floats2bfloat162_rn(l0, l1);
        sA[row * 132 + kp]            = *reinterpret_cast<uint32_t*>(&h2);
        sA[64 * 132 + row * 132 + kp] = *reinterpret_cast<uint32_t*>(&l2);
    }
    __syncthreads();

    const int lane = tid & 31;
    const int warp = tid >> 5;
    const int g    = lane >> 2;
    const int tg   = lane & 3;
    const int mtile   = warp >> 1;   // 0..3 (16 rows each)
    const int colhalf = warp & 1;    // 0..1 (64 cols each)

    // ldmatrix per-lane row/offset (canonical m16k16 x4 pattern)
    const int lrow = mtile * 16 + (lane & 7) + ((lane >> 3) & 1) * 8;
    const int lkof = ((lane >> 4) & 1) * 4;
    const uint32_t sA_base = (uint32_t)__cvta_generic_to_shared(sA);

    float d[8][4];
#pragma unroll
    for (int j = 0; j < 8; j++)
#pragma unroll
        for (int r = 0; r < 4; r++) d[j][r] = 0.f;

    const uint32_t* gWhi = g_Whi[mat];
    const uint32_t* gWlo = g_Wlo[mat];

    for (int ch = 0; ch < 4; ch++) {
        // Stage B chunk (k64 = 32 pairs x 128 cols, hi+lo) cooperatively.
#pragma unroll
        for (int i = 0; i < 8; i++) {
            int lin = tid + i * 256;         // 0..2047 uint4s
            int split = lin >> 10;           // warp-uniform per i
            int rem = lin & 1023;
            int r = rem >> 5, c4 = rem & 31;
            const uint4* src = (const uint4*)((split ? gWlo : gWhi) + ch * 32 * 128);
            uint4 v = src[r * 32 + c4];
            *(uint4*)(sB + split * 4352 + r * 136 + c4 * 4) = v;
        }
        __syncthreads();

#pragma unroll
        for (int t = 0; t < 4; t++) {
            const int kq = (ch * 4 + t) * 8;   // global k-pair base for this kstep
            uint32_t ah[4], al[4];
            {
                uint32_t addr = sA_base + (uint32_t)(lrow * 132 + kq + lkof) * 4u;
                asm volatile("ldmatrix.sync.aligned.m8n8.x4.shared.b16 {%0,%1,%2,%3}, [%4];"
                    : "=r"(ah[0]), "=r"(ah[1]), "=r"(ah[2]), "=r"(ah[3]) : "r"(addr));
                addr += 64u * 132u * 4u;
                asm volatile("ldmatrix.sync.aligned.m8n8.x4.shared.b16 {%0,%1,%2,%3}, [%4];"
                    : "=r"(al[0]), "=r"(al[1]), "=r"(al[2]), "=r"(al[3]) : "r"(addr));
            }
            const int rb0 = (t * 8 + tg) * 136;
            const int rb1 = (t * 8 + 4 + tg) * 136;
#pragma unroll
            for (int j = 0; j < 8; j++) {
                int col = colhalf * 64 + j * 8 + g;
                uint32_t bh0 = sB[rb0 + col];
                uint32_t bh1 = sB[rb1 + col];
                uint32_t bl0 = sB[4352 + rb0 + col];
                uint32_t bl1 = sB[4352 + rb1 + col];
                mma_bf16(d[j], ah, bh0, bh1);   // Ahi * Whi
                mma_bf16(d[j], al, bh0, bh1);   // Alo * Whi
                mma_bf16(d[j], ah, bl0, bl1);   // Ahi * Wlo
            }
        }
        __syncthreads();
    }

    // Epilogue: bias + ReLU + self-edge exclusion + row-sum (mean over 31)
    const int recv    = mtile >> 1;
    const int send_lo = (mtile & 1) * 16 + g;
    const int send_hi = send_lo + 8;
    const int nrecv   = n0 + recv;
    float t0[8], t1[8];
#pragma unroll
    for (int j = 0; j < 8; j++) {
        int c0 = colhalf * 64 + j * 8 + 2 * tg;
        float bb0 = b2[c0], bb1 = b2[c0 + 1];
        float v00 = fmaxf(d[j][0] + bb0, 0.f);
        float v01 = fmaxf(d[j][1] + bb1, 0.f);
        float v10 = fmaxf(d[j][2] + bb0, 0.f);
        float v11 = fmaxf(d[j][3] + bb1, 0.f);
        if (send_lo == nrecv) { v00 = 0.f; v01 = 0.f; }
        if (send_hi == nrecv) { v10 = 0.f; v11 = 0.f; }
        t0[j] = v00 + v10;
        t1[j] = v01 + v11;
    }
#pragma unroll
    for (int off = 4; off < 32; off <<= 1) {
#pragma unroll
        for (int j = 0; j < 8; j++) {
            t0[j] += __shfl_xor_sync(0xffffffffu, t0[j], off);
            t1[j] += __shfl_xor_sync(0xffffffffu, t1[j], off);
        }
    }
    if (lane < 4) {
#pragma unroll
        for (int j = 0; j < 8; j++) {
            int c0 = colhalf * 64 + j * 8 + 2 * lane;
            red[mtile * 128 + c0]     = t0[j];
            red[mtile * 128 + c0 + 1] = t1[j];
        }
    }
    __syncthreads();
    {
        int recvid = tid >> 7, c = tid & 127;
        g_msg[(bn0 + recvid) * 128 + c] =
            (red[recvid * 256 + c] + red[recvid * 256 + 128 + c]) * (1.0f / 31.0f);
    }
}

// ---------------------------------------------------------------------------
// Fused MLP kernel (encoder mlp1 / passing node MLP) + next-stage P/Q.
// 128 blocks x 4 rows, 256 threads.
// ---------------------------------------------------------------------------
template<int K1, bool FROM_MSG>
__global__ __launch_bounds__(256) void mlp_pq_kernel(
    const float* __restrict__ in_ext,
    const float* __restrict__ w1, const float* __restrict__ b1,   // [K1,256],[256]
    const float* __restrict__ w2, const float* __restrict__ b2,   // [256,128],[128]
    const float* __restrict__ w1n)                                // [256,256]
{
    __shared__ float in_s[4][K1];
    __shared__ float hid[4][EH];
    __shared__ float xs[4][NO];

    const int tid  = threadIdx.x;
    const int row0 = blockIdx.x * 4;
    const float* in = FROM_MSG ? g_msg : in_ext;

    for (int idx = tid; idx < 4 * K1; idx += 256) {
        int r = idx / K1, k = idx - r * K1;
        in_s[r][k] = in[(row0 + r) * K1 + k];
    }
    __syncthreads();

    // layer 1: K1 -> 256
    {
        const int j = tid;
        float acc[4] = {0.f, 0.f, 0.f, 0.f};
#pragma unroll 2
        for (int k = 0; k < K1; k++) {
            float w = w1[k * EH + j];
#pragma unroll
            for (int r = 0; r < 4; r++) acc[r] = fmaf(in_s[r][k], w, acc[r]);
        }
        float bb = b1[j];
#pragma unroll
        for (int r = 0; r < 4; r++) hid[r][j] = fmaxf(acc[r] + bb, 0.f);
    }
    __syncthreads();

    // layer 2: 256 -> 128
    {
        const int c = tid & 127, g2 = tid >> 7;
        float acc[2] = {0.f, 0.f};
#pragma unroll 2
        for (int k = 0; k < EH; k++) {
            float w = w2[k * NO + c];
#pragma unroll
            for (int r = 0; r < 2; r++) acc[r] = fmaf(hid[g2 * 2 + r][k], w, acc[r]);
        }
        float bb = b2[c];
#pragma unroll
        for (int r = 0; r < 2; r++) {
            float o = fmaxf(acc[r] + bb, 0.f);
            xs[g2 * 2 + r][c] = o;
            g_x[(row0 + g2 * 2 + r) * NO + c] = o;
        }
    }
    __syncthreads();

    // next-stage P/Q
    {
        const int j = tid;
        float accP[4] = {0,0,0,0}, accQ[4] = {0,0,0,0};
#pragma unroll 2
        for (int k = 0; k < NO; k++) {
            float wp = w1n[k * EH + j];
            float wq = w1n[(128 + k) * EH + j];
#pragma unroll
            for (int r = 0; r < 4; r++) {
                float xv = xs[r][k];
                accP[r] = fmaf(xv, wp, accP[r]);
                accQ[r] = fmaf(xv, wq, accQ[r]);
            }
        }
#pragma unroll
        for (int r = 0; r < 4; r++) {
            g_P[(row0 + r) * EH + j] = accP[r];
            g_Q[(row0 + r) * EH + j] = accQ[r];
        }
    }
}

// ---------------------------------------------------------------------------
// GRU step kernel: 128 blocks x 4 rows, 256 threads. Fused next-step P/Q.
// ---------------------------------------------------------------------------
__global__ __launch_bounds__(256) void gru_kernel(
    const float* __restrict__ dec_t,   // [512,3] slice for this t
    const float* __restrict__ w_hr, const float* __restrict__ w_hi, const float* __restrict__ w_hn,
    const float* __restrict__ w_ir, const float* __restrict__ b_ir,
    const float* __restrict__ w_ii, const float* __restrict__ b_ii,
    const float* __restrict__ w_in, const float* __restrict__ b_in,
    const float* __restrict__ w1n,    // de_w1 for next step
    float* __restrict__ out_t,        // outputs[t] = [512,128]
    float* __restrict__ state)        // final state (or nullptr)
{
    __shared__ float m_s[4][NO];
    __shared__ float h_s[4][NO];
    __shared__ float inp_s[4][3];
    __shared__ float hn_s[4][NO];

    const int tid  = threadIdx.x;
    const int row0 = blockIdx.x * 4;

#pragma unroll
    for (int i = 0; i < 2; i++) {
        int idx = tid + i * 256;
        int r = idx >> 7, k = idx & 127;
        m_s[r][k] = g_msg[(row0 + r) * NO + k];
        h_s[r][k] = g_x[(row0 + r) * NO + k];
    }
    if (tid < 12) {
        int r = tid / 3, j = tid - r * 3;
        inp_s[r][j] = dec_t[(row0 + r) * 3 + j];
    }
    __syncthreads();

    const int c = tid & 127, g2 = tid >> 7;
    float a_ir[2] = {0,0}, a_ii[2] = {0,0}, a_in[2] = {0,0};
    float a_hr[2] = {0,0}, a_hg[2] = {0,0}, a_hn[2] = {0,0};

#pragma unroll 2
    for (int k = 0; k < NO; k++) {
        float wir = w_ir[k * 128 + c], wii = w_ii[k * 128 + c], win = w_in[k * 128 + c];
        float whr = w_hr[k * 128 + c], whi = w_hi[k * 128 + c], whn = w_hn[k * 128 + c];
#pragma unroll
        for (int r = 0; r < 2; r++) {
            float m  = m_s[g2 * 2 + r][k];
            float hh = h_s[g2 * 2 + r][k];
            a_ir[r] = fmaf(m, wir, a_ir[r]);
            a_ii[r] = fmaf(m, wii, a_ii[r]);
            a_in[r] = fmaf(m, win, a_in[r]);
            a_hr[r] = fmaf(hh, whr, a_hr[r]);
            a_hg[r] = fmaf(hh, whi, a_hg[r]);
            a_hn[r] = fmaf(hh, whn, a_hn[r]);
        }
    }
#pragma unroll
    for (int j = 0; j < 3; j++) {
        float wir = w_ir[(128 + j) * 128 + c];
        float wii = w_ii[(128 + j) * 128 + c];
        float win = w_in[(128 + j) * 128 + c];
#pragma unroll
        for (int r = 0; r < 2; r++) {
            float x = inp_s[g2 * 2 + r][j];
            a_ir[r] = fmaf(x, wir, a_ir[r]);
            a_ii[r] = fmaf(x, wii, a_ii[r]);
            a_in[r] = fmaf(x, win, a_in[r]);
        }
    }

    float bir = b_ir[c], bii = b_ii[c], bin = b_in[c];
#pragma unroll
    for (int r = 0; r < 2; r++) {
        int row = g2 * 2 + r;
        float rr = 1.f / (1.f + expf(-(a_ir[r] + bir + a_hr[r])));
        float ii = 1.f / (1.f + expf(-(a_ii[r] + bii + a_hg[r])));
        float nn = tanhf(a_in[r] + bin + rr * a_hn[r]);
        float hv = (1.f - ii) * nn + ii * h_s[row][c];
        hn_s[row][c] = hv;
        int grow = row0 + row;
        g_x[grow * NO + c] = hv;
        out_t[grow * NO + c] = hv;
        if (state) state[grow * NO + c] = hv;
    }
    __syncthreads();

    // fused next-step P/Q from h'
    {
        const int j = tid;
        float accP[4] = {0,0,0,0}, accQ[4] = {0,0,0,0};
#pragma unroll 2
        for (int k = 0; k < NO; k++) {
            float wp = w1n[k * EH + j];
            float wq = w1n[(128 + k) * EH + j];
#pragma unroll
            for (int r = 0; r < 4; r++) {
                float xv = hn_s[r][k];
                accP[r] = fmaf(xv, wp, accP[r]);
                accQ[r] = fmaf(xv, wq, accQ[r]);
            }
        }
#pragma unroll
        for (int r = 0; r < 4; r++) {
            g_P[(row0 + r) * EH + j] = accP[r];
            g_Q[(row0 + r) * EH + j] = accQ[r];
        }
    }
}

// ---------------------------------------------------------------------------
extern "C" void kernel_launch(void* const* d_in, const int* in_sizes, int n_in,
                              void* d_out, int out_size)
{
    const float* enc_in = (const float*)d_in[0];   // [16,32,150]
    const float* dec_in = (const float*)d_in[1];   // [25,16,32,3]
    // d_in[2]=rec_encode, d_in[3]=send_encode (structure hardcoded)
    const float* enc_w1 = (const float*)d_in[4];
    const float* enc_b1 = (const float*)d_in[5];
    const float* enc_w2 = (const float*)d_in[6];
    const float* enc_b2 = (const float*)d_in[7];
    const float* pe_w1  = (const float*)d_in[8];
    const float* pe_b1  = (const float*)d_in[9];
    const float* pe_w2  = (const float*)d_in[10];
    const float* pe_b2  = (const float*)d_in[11];
    const float* pn_w1  = (const float*)d_in[12];
    const float* pn_b1  = (const float*)d_in[13];
    const float* pn_w2  = (const float*)d_in[14];
    const float* pn_b2  = (const float*)d_in[15];
    const float* de_w1  = (const float*)d_in[16];
    const float* de_b1  = (const float*)d_in[17];
    const float* de_w2  = (const float*)d_in[18];
    const float* de_b2  = (const float*)d_in[19];
    const float* w_hr   = (const float*)d_in[20];
    const float* w_hi   = (const float*)d_in[21];
    const float* w_hn   = (const float*)d_in[22];
    const float* w_ir   = (const float*)d_in[23];
    const float* b_ir   = (const float*)d_in[24];
    const float* w_ii   = (const float*)d_in[25];
    const float* b_ii   = (const float*)d_in[26];
    const float* w_in   = (const float*)d_in[27];
    const float* b_in   = (const float*)d_in[28];

    float* out   = (float*)d_out;
    float* state = out + (size_t)TSTEPS * NROWS * NO;  // outputs then final state

    // Allow >48KB dynamic smem for the tensor edge kernel (idempotent).
    cudaFuncSetAttribute(edge_mma_kernel,
                         cudaFuncAttributeMaxDynamicSharedMemorySize,
                         EDGE_SMEM_BYTES);

    // Pack edge layer-2 weights into bf16 hi/lo (mat 0 = pe_w2, mat 1 = de_w2)
    pack_w2_kernel<<<64, 512>>>(pe_w2, de_w2);

    // Encoder: mlp1, then P/Q for pass round 1 (pe_w1)
    mlp_pq_kernel<150, false><<<128, 256>>>(enc_in, enc_w1, enc_b1, enc_w2, enc_b2, pe_w1);

    // Two message-passing rounds
    for (int p = 0; p < 2; p++) {
        edge_mma_kernel<<<256, 256, EDGE_SMEM_BYTES>>>(0, pe_b1, pe_b2);
        mlp_pq_kernel<128, true><<<128, 256>>>(nullptr, pn_w1, pn_b1, pn_w2, pn_b2,
                                               (p == 0) ? pe_w1 : de_w1);
    }

    // Decoder: 25 GRU steps (edge message pass -> gated update -> next P/Q)
    for (int t = 0; t < TSTEPS; t++) {
        edge_mma_kernel<<<256, 256, EDGE_SMEM_BYTES>>>(1, de_b1, de_b2);
        gru_kernel<<<128, 256>>>(dec_in + (size_t)t * NROWS * 3,
                                 w_hr, w_hi, w_hn, w_ir, b_ir, w_ii, b_ii, w_in, b_in,
                                 de_w1,
                                 out + (size_t)t * NROWS * NO,
                                 (t == TSTEPS - 1) ? state : nullptr);
    }
}

// round 9
// speedup vs baseline: 1.4842x; 1.2061x over previous
#include <cuda_runtime.h>
#include <cuda_bf16.h>
#include <math.h>
#include <stdint.h>

// Problem constants
#define NROWS 512      // B*N = 16*32
#define NO 128         // node out dim
#define EH 256         // edge/node hidden dim
#define TSTEPS 25

// Scratch (device globals: no allocation allowed)
__device__ float g_x[NROWS * NO];        // node features / GRU hidden
__device__ float g_P[NROWS * EH];        // x @ W1_top   (send half)
__device__ float g_Q[NROWS * EH];        // x @ W1_bot   (rec half)
__device__ float g_msg[NROWS * NO];      // edge2node mean message
// Packed bf16 hi/lo of edge layer-2 weights (mat 0 = pe_w2, 1 = de_w2).
__device__ uint32_t g_Whi[2][128 * 128];
__device__ uint32_t g_Wlo[2][128 * 128];
// Transposed fp32 weights for latency-friendly float4 per-thread loads:
__device__ float g_WgT[6][128 * 128];    // gates [ir,ii,in,hr,hi,hn]: [c][k]
__device__ float g_W1nT[256 * 256];      // de_w1 transposed: [j][k]
__device__ float g_Wpe1T[256 * 256];     // pe_w1 transposed: [j][k]

// ---------------------------------------------------------------------------
// Pack pe_w2 / de_w2 into bf16 hi/lo k-pair format.
// ---------------------------------------------------------------------------
__global__ void pack_w2_kernel(const float* __restrict__ w2a,
                               const float* __restrict__ w2b)
{
    int idx = blockIdx.x * blockDim.x + threadIdx.x;   // < 32768
    int mat = idx >> 14;
    int rem = idx & 16383;
    int r = rem >> 7, n = rem & 127;
    const float* W = mat ? w2b : w2a;
    float w0 = W[(2 * r) * 128 + n];
    float w1 = W[(2 * r + 1) * 128 + n];
    __nv_bfloat162 h2 = __floats2bfloat162_rn(w0, w1);
    float l0 = w0 - __low2float(h2);
    float l1 = w1 - __high2float(h2);
    __nv_bfloat162 l2 = __floats2bfloat162_rn(l0, l1);
    g_Whi[mat][r * 128 + n] = *reinterpret_cast<uint32_t*>(&h2);
    g_Wlo[mat][r * 128 + n] = *reinterpret_cast<uint32_t*>(&l2);
}

// ---------------------------------------------------------------------------
// Transpose GRU gate weights (k<128 part) + de_w1 + pe_w1 into [col][k].
// ---------------------------------------------------------------------------
__global__ void pack_t_kernel(
    const float* __restrict__ w_ir, const float* __restrict__ w_ii,
    const float* __restrict__ w_in, const float* __restrict__ w_hr,
    const float* __restrict__ w_hi, const float* __restrict__ w_hn,
    const float* __restrict__ de_w1, const float* __restrict__ pe_w1)
{
    int idx = blockIdx.x * blockDim.x + threadIdx.x;   // < 229376
    if (idx < 98304) {
        int g = idx >> 14, rem = idx & 16383;
        int c = rem >> 7, k = rem & 127;
        const float* W;
        switch (g) {
            case 0: W = w_ir; break; case 1: W = w_ii; break;
            case 2: W = w_in; break; case 3: W = w_hr; break;
            case 4: W = w_hi; break; default: W = w_hn; break;
        }
        g_WgT[g][c * 128 + k] = W[k * 128 + c];
    } else if (idx < 163840) {
        int t = idx - 98304;
        int j = t >> 8, k = t & 255;
        g_W1nT[t] = de_w1[k * 256 + j];
    } else {
        int t = idx - 163840;
        int j = t >> 8, k = t & 255;
        g_Wpe1T[t] = pe_w1[k * 256 + j];
    }
}

__device__ __forceinline__ float dot4(float acc, float4 a, float4 b) {
    acc = fmaf(a.x, b.x, acc);
    acc = fmaf(a.y, b.y, acc);
    acc = fmaf(a.z, b.z, acc);
    acc = fmaf(a.w, b.w, acc);
    return acc;
}

__device__ __forceinline__ void mma_bf16(float (&d)[4], const uint32_t (&a)[4],
                                         uint32_t b0, uint32_t b1)
{
    asm volatile(
        "mma.sync.aligned.m16n8k16.row.col.f32.bf16.bf16.f32 "
        "{%0,%1,%2,%3}, {%4,%5,%6,%7}, {%8,%9}, {%0,%1,%2,%3};"
        : "+f"(d[0]), "+f"(d[1]), "+f"(d[2]), "+f"(d[3])
        : "r"(a[0]), "r"(a[1]), "r"(a[2]), "r"(a[3]), "r"(b0), "r"(b1));
}

// ---------------------------------------------------------------------------
// Tensor-core edge kernel (unchanged from R7 — fast).
// ---------------------------------------------------------------------------
#define EDGE_SMEM_BYTES ((2*64*132 + 2*32*136 + 512 + 512) * 4)

__global__ __launch_bounds__(256, 2) void edge_mma_kernel(
    int mat, const float* __restrict__ b1, const float* __restrict__ b2)
{
    extern __shared__ uint32_t sm[];
    uint32_t* sA  = sm;                          // hi [64][132] then lo [64][132]
    uint32_t* sB  = sm + 2 * 64 * 132;           // [2][32][136]
    float*    qb  = (float*)(sB + 2 * 32 * 136); // [2][256]
    float*    red = qb + 512;                    // [4][128]

    const int tid = threadIdx.x;
    const int blk = blockIdx.x;
    const int b   = blk >> 4;
    const int n0  = (blk & 15) * 2;
    const int bn0 = b * 32 + n0;

#pragma unroll
    for (int i = 0; i < 2; i++) {
        int idx = tid + i * 256;
        int r = idx >> 8, k = idx & 255;
        qb[idx] = g_Q[(bn0 + r) * EH + k] + b1[k];
    }
    __syncthreads();

#pragma unroll 4
    for (int i = 0; i < 32; i++) {
        int lin = tid + i * 256;
        int row = lin >> 7, kp = lin & 127;
        int recv = row >> 5, send = row & 31;
        float2 p = *(const float2*)(g_P + (b * 32 + send) * EH + 2 * kp);
        float2 q = *(const float2*)(qb + recv * 256 + 2 * kp);
        float a0 = fmaxf(p.x + q.x, 0.f);
        float a1 = fmaxf(p.y + q.y, 0.f);
        __nv_bfloat162 h2 = __floats2bfloat162_rn(a0, a1);
        float l0 = a0 - __low2float(h2);
        float l1 = a1 - __high2float(h2);
        __nv_bfloat162 l2 = __floats2bfloat162_rn(l0, l1);
        sA[row * 132 + kp]            = *reinterpret_cast<uint32_t*>(&h2);
        sA[64 * 132 + row * 132 + kp] = *reinterpret_cast<uint32_t*>(&l2);
    }
    __syncthreads();

    const int lane = tid & 31;
    const int warp = tid >> 5;
    const int g    = lane >> 2;
    const int tg   = lane & 3;
    const int mtile   = warp >> 1;
    const int colhalf = warp & 1;

    const int lrow = mtile * 16 + (lane & 7) + ((lane >> 3) & 1) * 8;
    const int lkof = ((lane >> 4) & 1) * 4;
    const uint32_t sA_base = (uint32_t)__cvta_generic_to_shared(sA);

    float d[8][4];
#pragma unroll
    for (int j = 0; j < 8; j++)
#pragma unroll
        for (int r = 0; r < 4; r++) d[j][r] = 0.f;

    const uint32_t* gWhi = g_Whi[mat];
    const uint32_t* gWlo = g_Wlo[mat];

    for (int ch = 0; ch < 4; ch++) {
#pragma unroll
        for (int i = 0; i < 8; i++) {
            int lin = tid + i * 256;
            int split = lin >> 10;
            int rem = lin & 1023;
            int r = rem >> 5, c4 = rem & 31;
            const uint4* src = (const uint4*)((split ? gWlo : gWhi) + ch * 32 * 128);
            uint4 v = src[r * 32 + c4];
            *(uint4*)(sB + split * 4352 + r * 136 + c4 * 4) = v;
        }
        __syncthreads();

#pragma unroll
        for (int t = 0; t < 4; t++) {
            const int kq = (ch * 4 + t) * 8;
            uint32_t ah[4], al[4];
            {
                uint32_t addr = sA_base + (uint32_t)(lrow * 132 + kq + lkof) * 4u;
                asm volatile("ldmatrix.sync.aligned.m8n8.x4.shared.b16 {%0,%1,%2,%3}, [%4];"
                    : "=r"(ah[0]), "=r"(ah[1]), "=r"(ah[2]), "=r"(ah[3]) : "r"(addr));
                addr += 64u * 132u * 4u;
                asm volatile("ldmatrix.sync.aligned.m8n8.x4.shared.b16 {%0,%1,%2,%3}, [%4];"
                    : "=r"(al[0]), "=r"(al[1]), "=r"(al[2]), "=r"(al[3]) : "r"(addr));
            }
            const int rb0 = (t * 8 + tg) * 136;
            const int rb1 = (t * 8 + 4 + tg) * 136;
#pragma unroll
            for (int j = 0; j < 8; j++) {
                int col = colhalf * 64 + j * 8 + g;
                uint32_t bh0 = sB[rb0 + col];
                uint32_t bh1 = sB[rb1 + col];
                uint32_t bl0 = sB[4352 + rb0 + col];
                uint32_t bl1 = sB[4352 + rb1 + col];
                mma_bf16(d[j], ah, bh0, bh1);
                mma_bf16(d[j], al, bh0, bh1);
                mma_bf16(d[j], ah, bl0, bl1);
            }
        }
        __syncthreads();
    }

    const int recv    = mtile >> 1;
    const int send_lo = (mtile & 1) * 16 + g;
    const int send_hi = send_lo + 8;
    const int nrecv   = n0 + recv;
    float t0[8], t1[8];
#pragma unroll
    for (int j = 0; j < 8; j++) {
        int c0 = colhalf * 64 + j * 8 + 2 * tg;
        float bb0 = b2[c0], bb1 = b2[c0 + 1];
        float v00 = fmaxf(d[j][0] + bb0, 0.f);
        float v01 = fmaxf(d[j][1] + bb1, 0.f);
        float v10 = fmaxf(d[j][2] + bb0, 0.f);
        float v11 = fmaxf(d[j][3] + bb1, 0.f);
        if (send_lo == nrecv) { v00 = 0.f; v01 = 0.f; }
        if (send_hi == nrecv) { v10 = 0.f; v11 = 0.f; }
        t0[j] = v00 + v10;
        t1[j] = v01 + v11;
    }
#pragma unroll
    for (int off = 4; off < 32; off <<= 1) {
#pragma unroll
        for (int j = 0; j < 8; j++) {
            t0[j] += __shfl_xor_sync(0xffffffffu, t0[j], off);
            t1[j] += __shfl_xor_sync(0xffffffffu, t1[j], off);
        }
    }
    if (lane < 4) {
#pragma unroll
        for (int j = 0; j < 8; j++) {
            int c0 = colhalf * 64 + j * 8 + 2 * lane;
            red[mtile * 128 + c0]     = t0[j];
            red[mtile * 128 + c0 + 1] = t1[j];
        }
    }
    __syncthreads();
    {
        int recvid = tid >> 7, c = tid & 127;
        g_msg[(bn0 + recvid) * 128 + c] =
            (red[recvid * 256 + c] + red[recvid * 256 + 128 + c]) * (1.0f / 31.0f);
    }
}

// ---------------------------------------------------------------------------
// Fused MLP kernel + next-stage P/Q. 128 blocks x 4 rows, 256 threads.
// which_w1n: 0 -> pe_w1 (transposed), 1 -> de_w1 (transposed).
// ---------------------------------------------------------------------------
template<int K1, bool FROM_MSG>
__global__ __launch_bounds__(256) void mlp_pq_kernel(
    const float* __restrict__ in_ext,
    const float* __restrict__ w1, const float* __restrict__ b1,   // [K1,256],[256]
    const float* __restrict__ w2, const float* __restrict__ b2,   // [256,128],[128]
    int which_w1n)
{
    __shared__ float in_s[4][K1];
    __shared__ float hid[4][EH];
    __shared__ float xs[4][NO];

    const int tid  = threadIdx.x;
    const int row0 = blockIdx.x * 4;
    const float* in = FROM_MSG ? g_msg : in_ext;

    for (int idx = tid; idx < 4 * K1; idx += 256) {
        int r = idx / K1, k = idx - r * K1;
        in_s[r][k] = in[(row0 + r) * K1 + k];
    }
    __syncthreads();

    // layer 1: K1 -> 256
    {
        const int j = tid;
        float acc[4] = {0.f, 0.f, 0.f, 0.f};
#pragma unroll 8
        for (int k = 0; k < K1; k++) {
            float w = w1[k * EH + j];
#pragma unroll
            for (int r = 0; r < 4; r++) acc[r] = fmaf(in_s[r][k], w, acc[r]);
        }
        float bb = b1[j];
#pragma unroll
        for (int r = 0; r < 4; r++) hid[r][j] = fmaxf(acc[r] + bb, 0.f);
    }
    __syncthreads();

    // layer 2: 256 -> 128
    {
        const int c = tid & 127, g2 = tid >> 7;
        float acc[2] = {0.f, 0.f};
#pragma unroll 8
        for (int k = 0; k < EH; k++) {
            float w = w2[k * NO + c];
#pragma unroll
            for (int r = 0; r < 2; r++) acc[r] = fmaf(hid[g2 * 2 + r][k], w, acc[r]);
        }
        float bb = b2[c];
#pragma unroll
        for (int r = 0; r < 2; r++) {
            float o = fmaxf(acc[r] + bb, 0.f);
            xs[g2 * 2 + r][c] = o;
            g_x[(row0 + g2 * 2 + r) * NO + c] = o;
        }
    }
    __syncthreads();

    // next-stage P/Q via transposed weights (float4 per-thread loads)
    {
        const int j = tid;
        const float* WT = which_w1n ? g_W1nT : g_Wpe1T;
        const float4* Wp = (const float4*)(WT + j * 256);
        const float4* Wq = (const float4*)(WT + j * 256 + 128);
        float accP[4] = {0,0,0,0}, accQ[4] = {0,0,0,0};
#pragma unroll 2
        for (int k4 = 0; k4 < 32; k4++) {
            float4 wp = Wp[k4];
            float4 wq = Wq[k4];
#pragma unroll
            for (int r = 0; r < 4; r++) {
                float4 x = ((const float4*)xs[r])[k4];
                accP[r] = dot4(accP[r], x, wp);
                accQ[r] = dot4(accQ[r], x, wq);
            }
        }
#pragma unroll
        for (int r = 0; r < 4; r++) {
            g_P[(row0 + r) * EH + j] = accP[r];
            g_Q[(row0 + r) * EH + j] = accQ[r];
        }
    }
}

// ---------------------------------------------------------------------------
// GRU step kernel: 128 blocks x 4 rows, 256 threads.
// Gate weights come from transposed device globals (float4 loads along k).
// w_ir/w_ii/w_in only used for the 3 decoder-input rows (128..130).
// ---------------------------------------------------------------------------
__global__ __launch_bounds__(256) void gru_kernel(
    const float* __restrict__ dec_t,   // [512,3] slice for this t
    const float* __restrict__ w_ir, const float* __restrict__ b_ir,
    const float* __restrict__ w_ii, const float* __restrict__ b_ii,
    const float* __restrict__ w_in, const float* __restrict__ b_in,
    float* __restrict__ out_t,         // outputs[t] = [512,128]
    float* __restrict__ state)         // final state (or nullptr)
{
    __shared__ float m_s[4][NO];
    __shared__ float h_s[4][NO];
    __shared__ float inp_s[4][3];
    __shared__ float hn_s[4][NO];

    const int tid  = threadIdx.x;
    const int row0 = blockIdx.x * 4;

#pragma unroll
    for (int i = 0; i < 2; i++) {
        int idx = tid + i * 256;
        int r = idx >> 7, k = idx & 127;
        m_s[r][k] = g_msg[(row0 + r) * NO + k];
        h_s[r][k] = g_x[(row0 + r) * NO + k];
    }
    if (tid < 12) {
        int r = tid / 3, j = tid - r * 3;
        inp_s[r][j] = dec_t[(row0 + r) * 3 + j];
    }
    __syncthreads();

    const int c = tid & 127, g2 = tid >> 7;
    // a[0..2][r]: m-based gates (ir,ii,in); a[3..5][r]: h-based (hr,hi,hn)
    float a[6][2];
#pragma unroll
    for (int g = 0; g < 6; g++) { a[g][0] = 0.f; a[g][1] = 0.f; }

    const float4* W0 = (const float4*)(g_WgT[0] + c * 128);
    const float4* W1p = (const float4*)(g_WgT[1] + c * 128);
    const float4* W2p = (const float4*)(g_WgT[2] + c * 128);
    const float4* W3p = (const float4*)(g_WgT[3] + c * 128);
    const float4* W4p = (const float4*)(g_WgT[4] + c * 128);
    const float4* W5p = (const float4*)(g_WgT[5] + c * 128);

#pragma unroll 2
    for (int k4 = 0; k4 < 32; k4++) {
        float4 wir = W0[k4], wii = W1p[k4], win = W2p[k4];
        float4 whr = W3p[k4], whi = W4p[k4], whn = W5p[k4];
#pragma unroll
        for (int r = 0; r < 2; r++) {
            float4 m = ((const float4*)m_s[g2 * 2 + r])[k4];
            float4 h = ((const float4*)h_s[g2 * 2 + r])[k4];
            a[0][r] = dot4(a[0][r], m, wir);
            a[1][r] = dot4(a[1][r], m, wii);
            a[2][r] = dot4(a[2][r], m, win);
            a[3][r] = dot4(a[3][r], h, whr);
            a[4][r] = dot4(a[4][r], h, whi);
            a[5][r] = dot4(a[5][r], h, whn);
        }
    }

    // decoder-input rows (k = 128..130, untransposed coalesced loads)
#pragma unroll
    for (int j = 0; j < 3; j++) {
        float wirv = w_ir[(128 + j) * 128 + c];
        float wiiv = w_ii[(128 + j) * 128 + c];
        float winv = w_in[(128 + j) * 128 + c];
#pragma unroll
        for (int r = 0; r < 2; r++) {
            float x = inp_s[g2 * 2 + r][j];
            a[0][r] = fmaf(x, wirv, a[0][r]);
            a[1][r] = fmaf(x, wiiv, a[1][r]);
            a[2][r] = fmaf(x, winv, a[2][r]);
        }
    }

    float bir = b_ir[c], bii = b_ii[c], bin = b_in[c];
#pragma unroll
    for (int r = 0; r < 2; r++) {
        int row = g2 * 2 + r;
        float rr = 1.f / (1.f + expf(-(a[0][r] + bir + a[3][r])));
        float ii = 1.f / (1.f + expf(-(a[1][r] + bii + a[4][r])));
        float nn = tanhf(a[2][r] + bin + rr * a[5][r]);
        float hv = (1.f - ii) * nn + ii * h_s[row][c];
        hn_s[row][c] = hv;
        int grow = row0 + row;
        g_x[grow * NO + c] = hv;
        out_t[grow * NO + c] = hv;
        if (state) state[grow * NO + c] = hv;
    }
    __syncthreads();

    // fused next-step P/Q from h' (de_w1 transposed)
    {
        const int j = tid;
        const float4* Wp = (const float4*)(g_W1nT + j * 256);
        const float4* Wq = (const float4*)(g_W1nT + j * 256 + 128);
        float accP[4] = {0,0,0,0}, accQ[4] = {0,0,0,0};
#pragma unroll 2
        for (int k4 = 0; k4 < 32; k4++) {
            float4 wp = Wp[k4];
            float4 wq = Wq[k4];
#pragma unroll
            for (int r = 0; r < 4; r++) {
                float4 x = ((const float4*)hn_s[r])[k4];
                accP[r] = dot4(accP[r], x, wp);
                accQ[r] = dot4(accQ[r], x, wq);
            }
        }
#pragma unroll
        for (int r = 0; r < 4; r++) {
            g_P[(row0 + r) * EH + j] = accP[r];
            g_Q[(row0 + r) * EH + j] = accQ[r];
        }
    }
}

// ---------------------------------------------------------------------------
extern "C" void kernel_launch(void* const* d_in, const int* in_sizes, int n_in,
                              void* d_out, int out_size)
{
    const float* enc_in = (const float*)d_in[0];   // [16,32,150]
    const float* dec_in = (const float*)d_in[1];   // [25,16,32,3]
    // d_in[2]=rec_encode, d_in[3]=send_encode (structure hardcoded)
    const float* enc_w1 = (const float*)d_in[4];
    const float* enc_b1 = (const float*)d_in[5];
    const float* enc_w2 = (const float*)d_in[6];
    const float* enc_b2 = (const float*)d_in[7];
    const float* pe_w1  = (const float*)d_in[8];
    const float* pe_b1  = (const float*)d_in[9];
    const float* pe_w2  = (const float*)d_in[10];
    const float* pe_b2  = (const float*)d_in[11];
    const float* pn_w1  = (const float*)d_in[12];
    const float* pn_b1  = (const float*)d_in[13];
    const float* pn_w2  = (const float*)d_in[14];
    const float* pn_b2  = (const float*)d_in[15];
    const float* de_w1  = (const float*)d_in[16];
    const float* de_b1  = (const float*)d_in[17];
    const float* de_w2  = (const float*)d_in[18];
    const float* de_b2  = (const float*)d_in[19];
    const float* w_hr   = (const float*)d_in[20];
    const float* w_hi   = (const float*)d_in[21];
    const float* w_hn   = (const float*)d_in[22];
    const float* w_ir   = (const float*)d_in[23];
    const float* b_ir   = (const float*)d_in[24];
    const float* w_ii   = (const float*)d_in[25];
    const float* b_ii   = (const float*)d_in[26];
    const float* w_in   = (const float*)d_in[27];
    const float* b_in   = (const float*)d_in[28];

    float* out   = (float*)d_out;
    float* state = out + (size_t)TSTEPS * NROWS * NO;  // outputs then final state

    cudaFuncSetAttribute(edge_mma_kernel,
                         cudaFuncAttributeMaxDynamicSharedMemorySize,
                         EDGE_SMEM_BYTES);

    // One-time packing (runs inside graph, cheap)
    pack_w2_kernel<<<64, 512>>>(pe_w2, de_w2);
    pack_t_kernel<<<448, 512>>>(w_ir, w_ii, w_in, w_hr, w_hi, w_hn, de_w1, pe_w1);

    // Encoder: mlp1, then P/Q for pass round 1 (pe_w1)
    mlp_pq_kernel<150, false><<<128, 256>>>(enc_in, enc_w1, enc_b1, enc_w2, enc_b2, 0);

    // Two message-passing rounds
    for (int p = 0; p < 2; p++) {
        edge_mma_kernel<<<256, 256, EDGE_SMEM_BYTES>>>(0, pe_b1, pe_b2);
        mlp_pq_kernel<128, true><<<128, 256>>>(nullptr, pn_w1, pn_b1, pn_w2, pn_b2,
                                               (p == 0) ? 0 : 1);
    }

    // Decoder: 25 GRU steps (edge message pass -> gated update -> next P/Q)
    for (int t = 0; t < TSTEPS; t++) {
        edge_mma_kernel<<<256, 256, EDGE_SMEM_BYTES>>>(1, de_b1, de_b2);
        gru_kernel<<<128, 256>>>(dec_in + (size_t)t * NROWS * 3,
                                 w_ir, b_ir, w_ii, b_ii, w_in, b_in,
                                 out + (size_t)t * NROWS * NO,
                                 (t == TSTEPS - 1) ? state : nullptr);
    }
}